// round 13
// baseline (speedup 1.0000x reference)
#include <cuda_runtime.h>
#include <cstdint>

#define T_STEPS 16
#define NN 12
#define BATCH 4096

#define ATW 2176          // A stage: 16 kw x 136 uint2
#define BTW 1152          // B stage: 16 kw x 72 uint2
#define S_ENC 34
#define S_DEC 16
#define S_H 13

__device__ float g_senc[BATCH * 400];
__device__ float g_sdec[BATCH * 400];
__device__ float g_hdec[BATCH * 400];
__device__ float g_wrbuf[BATCH * 144];

__device__ uint2 g_encin0[32 * S_ENC * ATW];
__device__ uint2 g_encin1[32 * S_ENC * ATW];
__device__ uint2 g_decin0[32 * S_DEC * ATW];
__device__ uint2 g_decin1[32 * S_DEC * ATW];
__device__ uint2 g_henct[32 * S_H * ATW];
__device__ uint2 g_hdect[32 * S_H * ATW];

__device__ uint2 g_wenc[25 * S_ENC * BTW];
__device__ uint2 g_wdec[25 * S_DEC * BTW];
__device__ uint2 g_wms[4 * S_H * BTW];
__device__ uint2 g_wwr[3 * S_H * BTW];
__device__ float g_cbenc[1664];
__device__ float g_cbdec[1664];
__device__ float g_cbms[256];
__device__ float g_cbwr[192];

__device__ __forceinline__ float fsigm(float x) {
    return __fdividef(1.0f, 1.0f + __expf(-x));
}
__device__ __forceinline__ float ftanh(float x) {
    float t = __expf(-2.0f * x);
    return (1.0f - t) * __fdividef(1.0f, 1.0f + t);
}
__device__ __forceinline__ void split2(float v0, float v1, uint32_t& hw, uint32_t& lw) {
    asm("cvt.rn.bf16x2.f32 %0, %1, %2;" : "=r"(hw) : "f"(v1), "f"(v0));
    float h0 = __uint_as_float(hw << 16);
    float h1 = __uint_as_float(hw & 0xffff0000u);
    asm("cvt.rn.bf16x2.f32 %0, %1, %2;" : "=r"(lw) : "f"(v1 - h1), "f"(v0 - h0));
}
__device__ __forceinline__ void mma_bf16(float* d, const uint32_t* a, const uint32_t* b) {
    asm volatile(
        "mma.sync.aligned.m16n8k16.row.col.f32.bf16.bf16.f32 "
        "{%0,%1,%2,%3}, {%4,%5,%6,%7}, {%8,%9}, {%0,%1,%2,%3};\n"
        : "+f"(d[0]), "+f"(d[1]), "+f"(d[2]), "+f"(d[3])
        : "r"(a[0]), "r"(a[1]), "r"(a[2]), "r"(a[3]), "r"(b[0]), "r"(b[1]));
}
// conflict-free swizzle: depends only on kw&3
__device__ __forceinline__ int swz4(int kw) {
    return ((4 - (kw & 3)) & 3) << 2;
}
__device__ __forceinline__ size_t a_idx(int S, int m, int kw) {
    return ((size_t)((m >> 7) * S + (kw >> 4))) * ATW +
           (kw & 15) * 136 + ((m & 127) ^ swz4(kw));
}

// ============ weight prep (single launch) ============
__device__ __forceinline__ float ldk(const float* Wa, const float* Wb, int K1,
                                     int K2, int src, int k) {
    if (k < K1) return Wa[(size_t)src * K1 + k];
    if (Wb && k < K1 + K2) return Wb[(size_t)src * K2 + (k - K1)];
    return 0.f;
}
__device__ void prep_body(const float* W1, int K1, const float* W2, int K2,
                          const float* b1, const float* b2,
                          int Nout, int S, int mode,
                          uint2* Bt, float* cb, int nt, int s, int tid, int nthr)
{
    // BNW = 64, BSTR = 72 for all B tiles
    for (int e = tid; e < 64 * 16; e += nthr) {
        int kwl = e >> 6, nl = e & 63;
        int n = nt * 64 + nl;
        float f0 = 0.f, f1 = 0.f, bv = 0.f;
        if (n < Nout) {
            int k0 = (s * 16 + kwl) * 2;
            if (mode == 1) {
                int src = (n & 3) * (Nout >> 2) + (n >> 2);
                f0 = ldk(W1, W2, K1, K2, src, k0);
                f1 = ldk(W1, W2, K1, K2, src, k0 + 1);
                bv = b1[src] + (b2 ? b2[src] : 0.f);
            } else if (mode == 2) {
                int src = n >> 1;
                const float* Ws = (n & 1) ? W2 : W1;
                f0 = ldk(Ws, nullptr, K1, 0, src, k0);
                f1 = ldk(Ws, nullptr, K1, 0, src, k0 + 1);
                bv = (n & 1) ? b2[src] : b1[src];
            } else {
                f0 = ldk(W1, W2, K1, K2, n, k0);
                f1 = ldk(W1, W2, K1, K2, n, k0 + 1);
                bv = b1[n] + (b2 ? b2[n] : 0.f);
            }
        }
        uint32_t h, l;
        split2(f0, f1, h, l);
        Bt[((size_t)(nt * S + s)) * BTW + kwl * 72 + (nl ^ swz4(kwl))] =
            make_uint2(h, l);
        if (s == 0 && kwl == 0) cb[nt * 64 + nl] = bv;
    }
}
// 25*34 enc + 25*16 dec + 4*13 ms + 3*13 wr = 850+400+52+39 = 1341 blocks
__global__ void prep_all(
    const float* __restrict__ w_enc_ih, const float* __restrict__ w_enc_hh,
    const float* __restrict__ b_enc_ih, const float* __restrict__ b_enc_hh,
    const float* __restrict__ w_dec_ih, const float* __restrict__ w_dec_hh,
    const float* __restrict__ b_dec_ih, const float* __restrict__ b_dec_hh,
    const float* __restrict__ w_mu, const float* __restrict__ b_mu,
    const float* __restrict__ w_sig, const float* __restrict__ b_sig,
    const float* __restrict__ w_write, const float* __restrict__ b_write,
    uint2* __restrict__ wenc, float* __restrict__ cbenc,
    uint2* __restrict__ wdec, float* __restrict__ cbdec,
    uint2* __restrict__ wms, float* __restrict__ cbms,
    uint2* __restrict__ wwr, float* __restrict__ cbwr)
{
    int idx = blockIdx.x;
    int tid = threadIdx.x, nthr = blockDim.x;
    if (idx < 850) {
        prep_body(w_enc_ih, 688, w_enc_hh, 400, b_enc_ih, b_enc_hh,
                  1600, S_ENC, 1, wenc, cbenc, idx / S_ENC, idx % S_ENC,
                  tid, nthr);
    } else if (idx < 1250) {
        int r2 = idx - 850;
        prep_body(w_dec_ih, 100, w_dec_hh, 400, b_dec_ih, b_dec_hh,
                  1600, S_DEC, 1, wdec, cbdec, r2 / S_DEC, r2 % S_DEC,
                  tid, nthr);
    } else if (idx < 1302) {
        int r2 = idx - 1250;
        prep_body(w_mu, 400, w_sig, 400, b_mu, b_sig,
                  200, S_H, 2, wms, cbms, r2 / S_H, r2 % S_H, tid, nthr);
    } else {
        int r2 = idx - 1302;
        prep_body(w_write, 400, nullptr, 0, b_write, nullptr,
                  144, S_H, 0, wwr, cbwr, r2 / S_H, r2 % S_H, tid, nthr);
    }
}

// ============ one-shot init ============
__global__ void zero_all()
{
    int i = blockIdx.x * blockDim.x + threadIdx.x;
    int st = gridDim.x * blockDim.x;
    uint2 z2 = make_uint2(0u, 0u);
    for (int k = i; k < BATCH * 400; k += st) {
        g_senc[k] = 0.f; g_sdec[k] = 0.f; g_hdec[k] = 0.f;
    }
    for (int k = i; k < 32 * S_ENC * ATW; k += st) {
        g_encin0[k] = z2; g_encin1[k] = z2;
    }
    for (int k = i; k < 32 * S_DEC * ATW; k += st) {
        g_decin0[k] = z2; g_decin1[k] = z2;
    }
    for (int k = i; k < 32 * S_H * ATW; k += st) {
        g_henct[k] = z2; g_hdect[k] = z2;
    }
}

// ============ GEMM, tile 128x64, 2-stage cp.async, 3 CTAs/SM ============
#define NSTG 2
#define STW (ATW + BTW)
#define GS (NSTG * STW * 8 + 1024)
#define CPA16(dst, src) \
    asm volatile("cp.async.cg.shared.global [%0], [%1], 16;" :: "r"(dst), "l"(src))

enum { EPI_NONE = 0, EPI_LSTM = 1, EPI_Z = 2 };

template<int EPI>
__global__ void __launch_bounds__(256, 3) gemm_k(
    const uint2* __restrict__ At, const uint2* __restrict__ Bt,
    const float* __restrict__ cb, int S, int Nout,
    float* __restrict__ Cout, int ldc,
    float* __restrict__ sptr, float* __restrict__ hfp,
    uint2* __restrict__ t1, int kwoff1, int S1,
    uint2* __restrict__ t2, int kwoff2, int S2,
    uint2* __restrict__ t3, int kwoff3, int S3,
    const float* __restrict__ epsp)
{
    constexpr int NI = 4;
    extern __shared__ uint2 smp[];
    float* sbias = (float*)(smp + NSTG * STW);

    const int tid = threadIdx.x, lane = tid & 31, w = tid >> 5;
    const int r = lane >> 2, j = lane & 3;
    const int wm = (w >> 1) * 32, wn = (w & 1) * 32;
    const int m0 = blockIdx.y * 128, n0 = blockIdx.x * 64;
    const uint2* Ag = At + (size_t)blockIdx.y * S * ATW;
    const uint2* Bg = Bt + (size_t)blockIdx.x * S * BTW;
    if (tid < 64) sbias[tid] = cb[n0 + tid];
    uint32_t smb = (uint32_t)__cvta_generic_to_shared(smp);

    const int aX = ((4 - j) & 3) << 2;
    const int pA0 = j * 1088 + ((wm + r) ^ aX) * 8;
    const int pA8 = j * 1088 + ((wm + r + 8) ^ aX) * 8;
    const int pB0 = j * 576 + ((wn + r) ^ aX) * 8;
    const int pB8 = j * 576 + ((wn + r + 8) ^ aX) * 8;

    float d[2][NI][4];
#pragma unroll
    for (int mi = 0; mi < 2; mi++)
#pragma unroll
        for (int ni = 0; ni < NI; ni++)
#pragma unroll
            for (int q = 0; q < 4; q++) d[mi][ni][q] = 0.f;

#define ISSUE(s, buf) {                                                    \
    const char* ga = (const char*)(Ag + (size_t)(s) * ATW);                \
    const char* gb = (const char*)(Bg + (size_t)(s) * BTW);                \
    uint32_t da = smb + (buf) * (STW * 8);                                 \
    uint32_t db = da + ATW * 8;                                            \
    for (int i = tid; i < 1088; i += 256) CPA16(da + i * 16, ga + i * 16); \
    for (int i = tid; i < 576; i += 256)  CPA16(db + i * 16, gb + i * 16); \
    asm volatile("cp.async.commit_group;" ::: "memory"); }

#define COMPUTE(buf) {                                                     \
    const char* cbse = (const char*)smp + (size_t)(buf) * (STW * 8);       \
    const char* A0 = cbse + pA0;                                           \
    const char* A8 = cbse + pA8;                                           \
    const char* B0 = cbse + ATW * 8 + pB0;                                 \
    const char* B8 = cbse + ATW * 8 + pB8;                                 \
    _Pragma("unroll")                                                      \
    for (int kk = 0; kk < 2; kk++) {                                       \
        uint32_t ah[2][4], al[2][4];                                       \
        _Pragma("unroll")                                                  \
        for (int mi = 0; mi < 2; mi++) {                                   \
            int c1 = mi * 128 + kk * 8704;                                 \
            uint2 w0 = *(const uint2*)(A0 + c1);                           \
            uint2 w1 = *(const uint2*)(A8 + c1);                           \
            uint2 w2 = *(const uint2*)(A0 + c1 + 4352);                    \
            uint2 w3 = *(const uint2*)(A8 + c1 + 4352);                    \
            ah[mi][0] = w0.x; ah[mi][1] = w1.x; ah[mi][2] = w2.x; ah[mi][3] = w3.x; \
            al[mi][0] = w0.y; al[mi][1] = w1.y; al[mi][2] = w2.y; al[mi][3] = w3.y; \
        }                                                                  \
        _Pragma("unroll")                                                  \
        for (int ni = 0; ni < NI; ni++) {                                  \
            const char* Bb = (ni & 1) ? B8 : B0;                           \
            int c2 = (ni >> 1) * 128 + kk * 4608;                          \
            uint2 u0 = *(const uint2*)(Bb + c2);                           \
            uint2 u1 = *(const uint2*)(Bb + c2 + 2304);                    \
            uint32_t bh[2] = {u0.x, u1.x};                                 \
            uint32_t bl[2] = {u0.y, u1.y};                                 \
            _Pragma("unroll")                                              \
            for (int mi = 0; mi < 2; mi++) {                               \
                mma_bf16(d[mi][ni], ah[mi], bl);                           \
                mma_bf16(d[mi][ni], al[mi], bh);                           \
                mma_bf16(d[mi][ni], ah[mi], bh);                           \
            }                                                              \
        }                                                                  \
    } }

    ISSUE(0, 0);
    for (int s = 0; s < S; s++) {
        asm volatile("cp.async.wait_group 0;" ::: "memory");
        __syncthreads();
        if (s + 1 < S) ISSUE(s + 1, (s + 1) & 1);
        COMPUTE(s & 1);
    }

    if (EPI == EPI_NONE) {
#pragma unroll
        for (int mi = 0; mi < 2; mi++) {
            int row = m0 + wm + mi * 16 + r;
#pragma unroll
            for (int ni = 0; ni < NI; ni++) {
                int col = wn + ni * 8 + 2 * j;
                int gcol = n0 + col;
                if (gcol < Nout) {
                    float bx = sbias[col], by = sbias[col + 1];
                    *(float2*)(Cout + (size_t)row * ldc + gcol) =
                        make_float2(d[mi][ni][0] + bx, d[mi][ni][1] + by);
                    *(float2*)(Cout + (size_t)(row + 8) * ldc + gcol) =
                        make_float2(d[mi][ni][2] + bx, d[mi][ni][3] + by);
                }
            }
        }
    } else if (EPI == EPI_LSTM) {
        const int NU = Nout >> 2;
#pragma unroll
        for (int mi = 0; mi < 2; mi++) {
            int rowA = m0 + wm + mi * 16 + r;
            int rowB = rowA + 8;
#pragma unroll
            for (int ni = 0; ni < NI; ni++) {
                int colA = wn + ni * 8 + 2 * j;
                float v0 = d[mi][ni][0] + sbias[colA];
                float v1 = d[mi][ni][1] + sbias[colA + 1];
                float v2 = d[mi][ni][2] + sbias[colA];
                float v3 = d[mi][ni][3] + sbias[colA + 1];
                float x0 = __shfl_xor_sync(0xffffffffu, v0, 1);
                float x1 = __shfl_xor_sync(0xffffffffu, v1, 1);
                float x2 = __shfl_xor_sync(0xffffffffu, v2, 1);
                float x3 = __shfl_xor_sync(0xffffffffu, v3, 1);
                int u = (n0 + colA) >> 2;
                bool act = ((j & 1) == 0) && (u < NU);
                float sA = 0.f, sB = 0.f;
                if (act) {
                    sA = sptr[(size_t)rowA * 400 + u];
                    sB = sptr[(size_t)rowB * 400 + u];
                }
                float cA = fsigm(v1) * sA + fsigm(v0) * ftanh(x0);
                float cB = fsigm(v3) * sB + fsigm(v2) * ftanh(x2);
                float hA = fsigm(x1) * ftanh(cA);
                float hB = fsigm(x3) * ftanh(cB);
                float hA2 = __shfl_xor_sync(0xffffffffu, hA, 2);
                float hB2 = __shfl_xor_sync(0xffffffffu, hB, 2);
                if (act) {
                    sptr[(size_t)rowA * 400 + u] = cA;
                    sptr[(size_t)rowB * 400 + u] = cB;
                    if (hfp) {
                        hfp[(size_t)rowA * 400 + u] = hA;
                        hfp[(size_t)rowB * 400 + u] = hB;
                    }
                }
                if (j == 0 && u < NU) {
                    int kw = u >> 1;
                    uint32_t hw, lw;
                    split2(hA, hA2, hw, lw);
                    uint2 wA = make_uint2(hw, lw);
                    split2(hB, hB2, hw, lw);
                    uint2 wB = make_uint2(hw, lw);
                    t1[a_idx(S1, rowA, kwoff1 + kw)] = wA;
                    t1[a_idx(S1, rowB, kwoff1 + kw)] = wB;
                    if (t2) {
                        t2[a_idx(S2, rowA, kwoff2 + kw)] = wA;
                        t2[a_idx(S2, rowB, kwoff2 + kw)] = wB;
                    }
                    if (t3) {
                        t3[a_idx(S3, rowA, kwoff3 + kw)] = wA;
                        t3[a_idx(S3, rowB, kwoff3 + kw)] = wB;
                    }
                }
            }
        }
    } else {  // EPI_Z
        const int NU = Nout >> 1;
#pragma unroll
        for (int mi = 0; mi < 2; mi++) {
            int rowA = m0 + wm + mi * 16 + r;
            int rowB = rowA + 8;
#pragma unroll
            for (int ni = 0; ni < NI; ni++) {
                int colA = wn + ni * 8 + 2 * j;
                float v0 = d[mi][ni][0] + sbias[colA];
                float v1 = d[mi][ni][1] + sbias[colA + 1];
                float v2 = d[mi][ni][2] + sbias[colA];
                float v3 = d[mi][ni][3] + sbias[colA + 1];
                int u = (n0 + colA) >> 1;
                float eA = 0.f, eB = 0.f;
                if (u < NU) {
                    eA = epsp[(size_t)rowA * 100 + u];
                    eB = epsp[(size_t)rowB * 100 + u];
                }
                float zA = v0 + __expf(v1) * eA;
                float zB = v2 + __expf(v3) * eB;
                float zA2 = __shfl_xor_sync(0xffffffffu, zA, 1);
                float zB2 = __shfl_xor_sync(0xffffffffu, zB, 1);
                if (((j & 1) == 0) && (u < NU)) {
                    int kw = u >> 1;
                    uint32_t hw, lw;
                    split2(zA, zA2, hw, lw);
                    t1[a_idx(S1, rowA, kwoff1 + kw)] = make_uint2(hw, lw);
                    split2(zB, zB2, hw, lw);
                    t1[a_idx(S1, rowB, kwoff1 + kw)] = make_uint2(hw, lw);
                }
            }
        }
    }
#undef ISSUE
#undef COMPUTE
}

// ============ fused canvas-write(prev step) + attention + glimpse ============
#define FRW_SMEM 50300
__global__ __launch_bounds__(256) void fused_rw(
    const float* __restrict__ x, float* __restrict__ c,
    const float* __restrict__ hdec, const float* __restrict__ wrg,
    const float* __restrict__ w_attn, const float* __restrict__ b_attn,
    uint2* __restrict__ et, int do_write)
{
    extern __shared__ float sm[];
    float* xs   = sm;
    float* xh   = sm + 4096;
    float* sFyT = sm + 8192;     // [a*16+n]
    float* sFyW = sm + 9216;     // [n*64+a]
    float* sFx  = sm + 9984;     // [n*68+a]
    float* tmp0 = sm + 10800;
    float* tmp1 = sm + 11568;
    float* sw   = sm + 12336;
    float* red  = sm + 12480;
    float* pp   = sm + 12520;
    float* rsx  = sm + 12528;
    float* rsyg = sm + 12540;
    float* rsyw = sm + 12552;

    int b = blockIdx.x, tid = threadIdx.x;
    int lane = tid & 31, wid = tid >> 5;
    const float* xb = x + (size_t)b * 4096;
    float* cbp = c + (size_t)b * 4096;
    const float* h = hdec + (size_t)b * 400;

    for (int i = tid; i < 1024; i += 256)
        *(float4*)&xs[i * 4] = *(const float4*)(xb + i * 4);
    if (tid < 144) sw[tid] = wrg[(size_t)b * 144 + tid];

    float acc[5] = {0.f, 0.f, 0.f, 0.f, 0.f};
    for (int k = tid; k < 400; k += 256) {
        float hv = h[k];
#pragma unroll
        for (int q = 0; q < 5; q++) acc[q] += hv * w_attn[q * 400 + k];
    }
#pragma unroll
    for (int q = 0; q < 5; q++)
#pragma unroll
        for (int off = 16; off > 0; off >>= 1)
            acc[q] += __shfl_xor_sync(0xffffffffu, acc[q], off);
    if (lane == 0)
#pragma unroll
        for (int q = 0; q < 5; q++) red[q * 8 + wid] = acc[q];
    __syncthreads();
    if (tid < 5) {
        float s = 0.f;
#pragma unroll
        for (int ww = 0; ww < 8; ww++) s += red[tid * 8 + ww];
        pp[tid] = s + b_attn[tid];
    }
    __syncthreads();

    float gx = 32.5f * (pp[0] + 1.0f);
    float gy = 32.5f * (pp[1] + 1.0f);
    float inv2s2 = __fdividef(1.0f, 2.0f * __expf(pp[2]));
    float delta = (63.0f / 11.0f) * __expf(pp[3]);
    float gamma = __expf(pp[4]);
    float invg = __expf(-pp[4]);

    for (int e = tid; e < 768; e += 256) {
        int n = e >> 6, a = e & 63;
        float fa = (float)a;
        float base = ((float)n - 6.5f) * delta;
        float ty = (fa - (base + gy)) * inv2s2;
        float fy = __expf(-ty * ty);
        sFyT[a * 16 + n] = fy;
        sFyW[n * 64 + a] = fy;
        float tx = (fa - (base + gx)) * inv2s2;
        sFx[n * 68 + a] = __expf(-tx * tx);
    }
    __syncthreads();
    if (tid < 12) {
        float s = 0.f;
        for (int a = 0; a < 64; a++) s += sFx[tid * 68 + a];
        rsx[tid] = __fdividef(1.0f, s + 1e-9f);
    } else if (tid >= 16 && tid < 28) {
        int n = tid - 16;
        float s = 0.f;
        for (int a = 0; a < 64; a++) s += sFyW[n * 64 + a];
        float inv = __fdividef(1.0f, s + 1e-9f);
        rsyg[n] = gamma * inv;
        rsyw[n] = invg * inv;
    }
    __syncthreads();
    for (int e = tid; e < 768; e += 256) {
        int n = e >> 6, a = e & 63;
        sFx[n * 68 + a] *= rsx[n];
        sFyT[a * 16 + n] *= rsyg[n];
        sFyW[n * 64 + a] *= rsyw[n];
    }
    __syncthreads();

    for (int e = tid; e < 768; e += 256) {
        int m = e >> 6, Bi = e & 63;
        float s = 0.f;
#pragma unroll
        for (int n = 0; n < NN; n++) s += sFyW[n * 64 + Bi] * sw[n * NN + m];
        tmp0[e] = s;
    }
    __syncthreads();

    for (int p = tid; p < 1024; p += 256) {
        int Bi = p >> 4, aq = p & 15;
        int idx = Bi * 64 + aq * 4;
        float4 cv;
        if (do_write) {
            float4 a4 = make_float4(0.f, 0.f, 0.f, 0.f);
#pragma unroll
            for (int m = 0; m < NN; m++) {
                float t = tmp0[m * 64 + Bi];
                float4 f4 = *(const float4*)&sFx[m * 68 + aq * 4];
                a4.x += t * f4.x; a4.y += t * f4.y;
                a4.z += t * f4.z; a4.w += t * f4.w;
            }
            cv = *(float4*)&cbp[idx];
            cv.x += a4.x; cv.y += a4.y; cv.z += a4.z; cv.w += a4.w;
        } else {
            cv = make_float4(0.f, 0.f, 0.f, 0.f);
        }
        *(float4*)&cbp[idx] = cv;
        float4 xv = *(const float4*)&xs[idx];
        float4 hv;
        hv.x = xv.x - fsigm(cv.x);
        hv.y = xv.y - fsigm(cv.y);
        hv.z = xv.z - fsigm(cv.z);
        hv.w = xv.w - fsigm(cv.w);
        *(float4*)&xh[idx] = hv;
    }
    __syncthreads();

    if (tid < 64) {
        int img = tid >> 5, half = (tid >> 4) & 1, aq = tid & 15;
        const float* src = img ? xh : xs;
        float* tdst = img ? tmp1 : tmp0;
        float a6[6][4];
#pragma unroll
        for (int nn = 0; nn < 6; nn++)
#pragma unroll
            for (int q = 0; q < 4; q++) a6[nn][q] = 0.f;
        for (int bi = 0; bi < 64; bi++) {
            float4 sv = *(const float4*)&src[bi * 64 + aq * 4];
            const float* fp = &sFyT[bi * 16 + half * 6];
#pragma unroll
            for (int nn = 0; nn < 6; nn++) {
                float f = fp[nn];
                a6[nn][0] += f * sv.x; a6[nn][1] += f * sv.y;
                a6[nn][2] += f * sv.z; a6[nn][3] += f * sv.w;
            }
        }
#pragma unroll
        for (int nn = 0; nn < 6; nn++)
            *(float4*)&tdst[(half * 6 + nn) * 64 + aq * 4] =
                make_float4(a6[nn][0], a6[nn][1], a6[nn][2], a6[nn][3]);
    }
    __syncthreads();

    for (int p = tid; p < 144; p += 256) {
        int img = p >= 72;
        int rem0 = 2 * p - img * 144;
        int n0q = rem0 / 12, m0q = rem0 - 12 * n0q;
        int n1q = n0q, m1q = m0q + 1;
        if (m1q == 12) { n1q++; m1q = 0; }
        const float* tsel = img ? tmp1 : tmp0;
        float s0 = 0.f, s1 = 0.f;
#pragma unroll
        for (int aq = 0; aq < 16; aq++) {
            float4 t0 = *(const float4*)&tsel[n0q * 64 + aq * 4];
            float4 f0 = *(const float4*)&sFx[m0q * 68 + aq * 4];
            s0 += t0.x * f0.x + t0.y * f0.y + t0.z * f0.z + t0.w * f0.w;
            float4 t1 = *(const float4*)&tsel[n1q * 64 + aq * 4];
            float4 f1 = *(const float4*)&sFx[m1q * 68 + aq * 4];
            s1 += t1.x * f1.x + t1.y * f1.y + t1.z * f1.z + t1.w * f1.w;
        }
        uint32_t hh, ll;
        split2(s0, s1, hh, ll);
        et[a_idx(S_ENC, b, p)] = make_uint2(hh, ll);
    }
}

// ============ final canvas write ============
__global__ __launch_bounds__(256) void write_final(
    const float* __restrict__ wrg, const float* __restrict__ hdec,
    const float* __restrict__ w_attn, const float* __restrict__ b_attn,
    float* __restrict__ c)
{
    int b = blockIdx.x;
    int tid = threadIdx.x;
    int lane = tid & 31, wid = tid >> 5;

    __shared__ float sFy[NN * 64], sFx[NN * 64];
    __shared__ float sw[NN * NN];
    __shared__ float tmpv[NN * 64];
    __shared__ float red[5][8], pp[5], rsx[12], rsy[12];

    const float* h = hdec + (size_t)b * 400;

    float acc[5] = {0.f, 0.f, 0.f, 0.f, 0.f};
    for (int k = tid; k < 400; k += 256) {
        float hv = h[k];
#pragma unroll
        for (int q = 0; q < 5; q++) acc[q] += hv * w_attn[q * 400 + k];
    }
#pragma unroll
    for (int q = 0; q < 5; q++)
#pragma unroll
        for (int off = 16; off > 0; off >>= 1)
            acc[q] += __shfl_xor_sync(0xffffffffu, acc[q], off);
    if (lane == 0)
#pragma unroll
        for (int q = 0; q < 5; q++) red[q][wid] = acc[q];
    if (tid < NN * NN) sw[tid] = wrg[(size_t)b * (NN * NN) + tid];
    __syncthreads();
    if (tid < 5) {
        float s = 0.f;
#pragma unroll
        for (int ww = 0; ww < 8; ww++) s += red[tid][ww];
        pp[tid] = s + b_attn[tid];
    }
    __syncthreads();

    float gx = 32.5f * (pp[0] + 1.0f);
    float gy = 32.5f * (pp[1] + 1.0f);
    float inv2s2 = __fdividef(1.0f, 2.0f * __expf(pp[2]));
    float delta = (63.0f / 11.0f) * __expf(pp[3]);
    float invgamma = __expf(-pp[4]);

    for (int e = tid; e < 768; e += 256) {
        int n = e >> 6, a = e & 63;
        float fa = (float)a;
        float base = ((float)n - 6.5f) * delta;
        float ty = (fa - (base + gy)) * inv2s2;
        sFy[n * 64 + a] = __expf(-ty * ty);
        float tx = (fa - (base + gx)) * inv2s2;
        sFx[n * 64 + a] = __expf(-tx * tx);
    }
    __syncthreads();
    if (tid < 12) {
        float s = 0.f;
        for (int a = 0; a < 64; a++) s += sFx[tid * 64 + a];
        rsx[tid] = __fdividef(1.0f, s + 1e-9f);
    } else if (tid >= 16 && tid < 28) {
        int n = tid - 16;
        float s = 0.f;
        for (int a = 0; a < 64; a++) s += sFy[n * 64 + a];
        rsy[n] = invgamma * __fdividef(1.0f, s + 1e-9f);
    }
    __syncthreads();
    for (int e = tid; e < 768; e += 256) {
        int n = e >> 6, a = e & 63;
        sFx[n * 64 + a] *= rsx[n];
        sFy[n * 64 + a] *= rsy[n];
    }
    __syncthreads();

    for (int e = tid; e < NN * 64; e += 256) {
        int m = e >> 6, Bi = e & 63;
        float s = 0.f;
#pragma unroll
        for (int n = 0; n < NN; n++) s += sFy[n * 64 + Bi] * sw[n * NN + m];
        tmpv[e] = s;
    }
    __syncthreads();

    float* cbp = c + (size_t)b * 4096;
    for (int p = tid; p < 1024; p += 256) {
        int Bi = p >> 4, aq = p & 15;
        float4 a4 = make_float4(0.f, 0.f, 0.f, 0.f);
#pragma unroll
        for (int m = 0; m < NN; m++) {
            float t = tmpv[m * 64 + Bi];
            float4 f4 = *(const float4*)&sFx[m * 64 + aq * 4];
            a4.x += t * f4.x; a4.y += t * f4.y;
            a4.z += t * f4.z; a4.w += t * f4.w;
        }
        float4 cv = *(float4*)&cbp[Bi * 64 + aq * 4];
        cv.x += a4.x; cv.y += a4.y; cv.z += a4.z; cv.w += a4.w;
        *(float4*)&cbp[Bi * 64 + aq * 4] = cv;
    }
}

// ============ host ============
extern "C" void kernel_launch(void* const* d_in, const int* in_sizes, int n_in,
                              void* d_out, int out_size)
{
    const float* x        = (const float*)d_in[0];
    const float* eps      = (const float*)d_in[1];
    const float* w_enc_ih = (const float*)d_in[2];
    const float* w_enc_hh = (const float*)d_in[3];
    const float* b_enc_ih = (const float*)d_in[4];
    const float* b_enc_hh = (const float*)d_in[5];
    const float* w_dec_ih = (const float*)d_in[6];
    const float* w_dec_hh = (const float*)d_in[7];
    const float* b_dec_ih = (const float*)d_in[8];
    const float* b_dec_hh = (const float*)d_in[9];
    const float* w_mu     = (const float*)d_in[10];
    const float* b_mu     = (const float*)d_in[11];
    const float* w_sig    = (const float*)d_in[12];
    const float* b_sig    = (const float*)d_in[13];
    const float* w_attn   = (const float*)d_in[14];
    const float* b_attn   = (const float*)d_in[15];
    const float* w_write  = (const float*)d_in[16];
    const float* b_write  = (const float*)d_in[17];
    float* c = (float*)d_out;

    float *p_senc, *p_sdec, *p_hdec, *p_wrbuf;
    uint2 *p_enc0, *p_enc1, *p_dec0, *p_dec1, *p_henct, *p_hdect;
    uint2 *p_wenc, *p_wdec, *p_wms, *p_wwr;
    float *p_cbenc, *p_cbdec, *p_cbms, *p_cbwr;
    cudaGetSymbolAddress((void**)&p_senc,  g_senc);
    cudaGetSymbolAddress((void**)&p_sdec,  g_sdec);
    cudaGetSymbolAddress((void**)&p_hdec,  g_hdec);
    cudaGetSymbolAddress((void**)&p_wrbuf, g_wrbuf);
    cudaGetSymbolAddress((void**)&p_enc0,  g_encin0);
    cudaGetSymbolAddress((void**)&p_enc1,  g_encin1);
    cudaGetSymbolAddress((void**)&p_dec0,  g_decin0);
    cudaGetSymbolAddress((void**)&p_dec1,  g_decin1);
    cudaGetSymbolAddress((void**)&p_henct, g_henct);
    cudaGetSymbolAddress((void**)&p_hdect, g_hdect);
    cudaGetSymbolAddress((void**)&p_wenc,  g_wenc);
    cudaGetSymbolAddress((void**)&p_wdec,  g_wdec);
    cudaGetSymbolAddress((void**)&p_wms,   g_wms);
    cudaGetSymbolAddress((void**)&p_wwr,   g_wwr);
    cudaGetSymbolAddress((void**)&p_cbenc, g_cbenc);
    cudaGetSymbolAddress((void**)&p_cbdec, g_cbdec);
    cudaGetSymbolAddress((void**)&p_cbms,  g_cbms);
    cudaGetSymbolAddress((void**)&p_cbwr,  g_cbwr);

    cudaFuncSetAttribute(gemm_k<EPI_LSTM>,
                         cudaFuncAttributeMaxDynamicSharedMemorySize, GS);
    cudaFuncSetAttribute(gemm_k<EPI_Z>,
                         cudaFuncAttributeMaxDynamicSharedMemorySize, GS);
    cudaFuncSetAttribute(gemm_k<EPI_NONE>,
                         cudaFuncAttributeMaxDynamicSharedMemorySize, GS);
    cudaFuncSetAttribute(fused_rw,
                         cudaFuncAttributeMaxDynamicSharedMemorySize, FRW_SMEM);

    zero_all<<<4096, 256>>>();
    prep_all<<<1341, 256>>>(w_enc_ih, w_enc_hh, b_enc_ih, b_enc_hh,
                            w_dec_ih, w_dec_hh, b_dec_ih, b_dec_hh,
                            w_mu, b_mu, w_sig, b_sig, w_write, b_write,
                            p_wenc, p_cbenc, p_wdec, p_cbdec,
                            p_wms, p_cbms, p_wwr, p_cbwr);

    dim3 grid_gate(25, 32), grid_ms(4, 32), grid_wr(3, 32);

    for (int t = 0; t < T_STEPS; t++) {
        uint2* enc_p = (t & 1) ? p_enc1 : p_enc0;
        uint2* enc_q = (t & 1) ? p_enc0 : p_enc1;
        uint2* dec_p = (t & 1) ? p_dec1 : p_dec0;
        uint2* dec_q = (t & 1) ? p_dec0 : p_dec1;

        fused_rw<<<BATCH, 256, FRW_SMEM>>>(x, c, p_hdec, p_wrbuf,
                                           w_attn, b_attn, enc_p, t > 0);
        // encoder gates + fused LSTM  <-- ncu target
        gemm_k<EPI_LSTM><<<grid_gate, 256, GS>>>(
            enc_p, p_wenc, p_cbenc, S_ENC, 1600,
            nullptr, 0, p_senc, nullptr,
            p_henct, 0, S_H, enc_q, 344, S_ENC, nullptr, 0, 0, nullptr);
        gemm_k<EPI_Z><<<grid_ms, 256, GS>>>(
            p_henct, p_wms, p_cbms, S_H, 200,
            nullptr, 0, nullptr, nullptr,
            dec_p, 0, S_DEC, nullptr, 0, 0, nullptr, 0, 0,
            eps + (size_t)t * BATCH * 100);
        gemm_k<EPI_LSTM><<<grid_gate, 256, GS>>>(
            dec_p, p_wdec, p_cbdec, S_DEC, 1600,
            nullptr, 0, p_sdec, p_hdec,
            dec_q, 50, S_DEC, enc_q, 144, S_ENC, p_hdect, 0, S_H, nullptr);
        gemm_k<EPI_NONE><<<grid_wr, 256, GS>>>(
            p_hdect, p_wwr, p_cbwr, S_H, 144,
            p_wrbuf, 144, nullptr, nullptr,
            nullptr, 0, 0, nullptr, 0, 0, nullptr, 0, 0, nullptr);
    }
    write_final<<<BATCH, 256>>>(p_wrbuf, p_hdec, w_attn, b_attn, c);
}

// round 14
// speedup vs baseline: 1.0177x; 1.0177x over previous
#include <cuda_runtime.h>
#include <cstdint>

#define T_STEPS 16
#define NN 12
#define BATCH 4096

#define ATW 2176          // A stage: 16 kw x 136 uint2
#define S_ENC 34
#define S_DEC 16
#define S_H 13

#define PDL_WAIT() asm volatile("griddepcontrol.wait;" ::: "memory")

__device__ float g_senc[BATCH * 400];
__device__ float g_sdec[BATCH * 400];
__device__ float g_hdec[BATCH * 400];
__device__ float g_wrbuf[BATCH * 144];

__device__ uint2 g_encin0[32 * S_ENC * ATW];
__device__ uint2 g_encin1[32 * S_ENC * ATW];
__device__ uint2 g_decin0[32 * S_DEC * ATW];
__device__ uint2 g_decin1[32 * S_DEC * ATW];
__device__ uint2 g_henct[32 * S_H * ATW];
__device__ uint2 g_hdect[32 * S_H * ATW];

__device__ uint2 g_wenc[13 * S_ENC * 2176];
__device__ uint2 g_wdec[13 * S_DEC * 2176];
__device__ uint2 g_wms[4 * S_H * 1152];
__device__ uint2 g_wwr[3 * S_H * 1152];
__device__ float g_cbenc[1664];
__device__ float g_cbdec[1664];
__device__ float g_cbms[256];
__device__ float g_cbwr[192];

__device__ __forceinline__ float fsigm(float x) {
    return __fdividef(1.0f, 1.0f + __expf(-x));
}
__device__ __forceinline__ float ftanh(float x) {
    float t = __expf(-2.0f * x);
    return (1.0f - t) * __fdividef(1.0f, 1.0f + t);
}
__device__ __forceinline__ void split2(float v0, float v1, uint32_t& hw, uint32_t& lw) {
    asm("cvt.rn.bf16x2.f32 %0, %1, %2;" : "=r"(hw) : "f"(v1), "f"(v0));
    float h0 = __uint_as_float(hw << 16);
    float h1 = __uint_as_float(hw & 0xffff0000u);
    asm("cvt.rn.bf16x2.f32 %0, %1, %2;" : "=r"(lw) : "f"(v1 - h1), "f"(v0 - h0));
}
__device__ __forceinline__ void mma_bf16(float* d, const uint32_t* a, const uint32_t* b) {
    asm volatile(
        "mma.sync.aligned.m16n8k16.row.col.f32.bf16.bf16.f32 "
        "{%0,%1,%2,%3}, {%4,%5,%6,%7}, {%8,%9}, {%0,%1,%2,%3};\n"
        : "+f"(d[0]), "+f"(d[1]), "+f"(d[2]), "+f"(d[3])
        : "r"(a[0]), "r"(a[1]), "r"(a[2]), "r"(a[3]), "r"(b[0]), "r"(b[1]));
}
__device__ __forceinline__ int swz4(int kw) {
    return ((4 - (kw & 3)) & 3) << 2;
}
__device__ __forceinline__ size_t a_idx(int S, int m, int kw) {
    return ((size_t)((m >> 7) * S + (kw >> 4))) * ATW +
           (kw & 15) * 136 + ((m & 127) ^ swz4(kw));
}

// ============ weight prep (single launch) ============
__device__ __forceinline__ float ldk(const float* Wa, const float* Wb, int K1,
                                     int K2, int src, int k) {
    if (k < K1) return Wa[(size_t)src * K1 + k];
    if (Wb && k < K1 + K2) return Wb[(size_t)src * K2 + (k - K1)];
    return 0.f;
}
__device__ void prep_body(const float* W1, int K1, const float* W2, int K2,
                          const float* b1, const float* b2,
                          int Nout, int S, int mode, int BNW,
                          uint2* Bt, float* cb, int nt, int s, int tid, int nthr)
{
    int BSTR = (BNW == 128) ? 136 : 72;
    int elems = BNW * 16;
    for (int e = tid; e < elems; e += nthr) {
        int kwl = e / BNW, nl = e - kwl * BNW;
        int n = nt * BNW + nl;
        float f0 = 0.f, f1 = 0.f, bv = 0.f;
        if (n < Nout) {
            int k0 = (s * 16 + kwl) * 2;
            if (mode == 1) {
                int src = (n & 3) * (Nout >> 2) + (n >> 2);
                f0 = ldk(W1, W2, K1, K2, src, k0);
                f1 = ldk(W1, W2, K1, K2, src, k0 + 1);
                bv = b1[src] + (b2 ? b2[src] : 0.f);
            } else if (mode == 2) {
                int src = n >> 1;
                const float* Ws = (n & 1) ? W2 : W1;
                f0 = ldk(Ws, nullptr, K1, 0, src, k0);
                f1 = ldk(Ws, nullptr, K1, 0, src, k0 + 1);
                bv = (n & 1) ? b2[src] : b1[src];
            } else {
                f0 = ldk(W1, W2, K1, K2, n, k0);
                f1 = ldk(W1, W2, K1, K2, n, k0 + 1);
                bv = b1[n] + (b2 ? b2[n] : 0.f);
            }
        }
        uint32_t h, l;
        split2(f0, f1, h, l);
        Bt[((size_t)(nt * S + s)) * (16 * BSTR) + kwl * BSTR +
           (nl ^ swz4(kwl))] = make_uint2(h, l);
        if (s == 0 && kwl == 0) cb[nt * BNW + nl] = bv;
    }
}
__global__ void prep_all(
    const float* __restrict__ w_enc_ih, const float* __restrict__ w_enc_hh,
    const float* __restrict__ b_enc_ih, const float* __restrict__ b_enc_hh,
    const float* __restrict__ w_dec_ih, const float* __restrict__ w_dec_hh,
    const float* __restrict__ b_dec_ih, const float* __restrict__ b_dec_hh,
    const float* __restrict__ w_mu, const float* __restrict__ b_mu,
    const float* __restrict__ w_sig, const float* __restrict__ b_sig,
    const float* __restrict__ w_write, const float* __restrict__ b_write,
    uint2* __restrict__ wenc, float* __restrict__ cbenc,
    uint2* __restrict__ wdec, float* __restrict__ cbdec,
    uint2* __restrict__ wms, float* __restrict__ cbms,
    uint2* __restrict__ wwr, float* __restrict__ cbwr)
{
    int idx = blockIdx.x;
    int tid = threadIdx.x, nthr = blockDim.x;
    if (idx < 442) {
        prep_body(w_enc_ih, 688, w_enc_hh, 400, b_enc_ih, b_enc_hh,
                  1600, S_ENC, 1, 128, wenc, cbenc, idx / S_ENC, idx % S_ENC,
                  tid, nthr);
    } else if (idx < 650) {
        int r2 = idx - 442;
        prep_body(w_dec_ih, 100, w_dec_hh, 400, b_dec_ih, b_dec_hh,
                  1600, S_DEC, 1, 128, wdec, cbdec, r2 / S_DEC, r2 % S_DEC,
                  tid, nthr);
    } else if (idx < 702) {
        int r2 = idx - 650;
        prep_body(w_mu, 400, w_sig, 400, b_mu, b_sig,
                  200, S_H, 2, 64, wms, cbms, r2 / S_H, r2 % S_H, tid, nthr);
    } else {
        int r2 = idx - 702;
        prep_body(w_write, 400, nullptr, 0, b_write, nullptr,
                  144, S_H, 0, 64, wwr, cbwr, r2 / S_H, r2 % S_H, tid, nthr);
    }
}

// ============ one-shot init ============
__global__ void zero_all()
{
    int i = blockIdx.x * blockDim.x + threadIdx.x;
    int st = gridDim.x * blockDim.x;
    uint2 z2 = make_uint2(0u, 0u);
    for (int k = i; k < BATCH * 400; k += st) {
        g_senc[k] = 0.f; g_sdec[k] = 0.f; g_hdec[k] = 0.f;
    }
    for (int k = i; k < 32 * S_ENC * ATW; k += st) {
        g_encin0[k] = z2; g_encin1[k] = z2;
    }
    for (int k = i; k < 32 * S_DEC * ATW; k += st) {
        g_decin0[k] = z2; g_decin1[k] = z2;
    }
    for (int k = i; k < 32 * S_H * ATW; k += st) {
        g_henct[k] = z2; g_hdect[k] = z2;
    }
}

// ============ templated GEMM with fused epilogues (R12 config) ============
#define NSTG 3
#define CPA16(dst, src) \
    asm volatile("cp.async.cg.shared.global [%0], [%1], 16;" :: "r"(dst), "l"(src))

enum { EPI_NONE = 0, EPI_LSTM = 1, EPI_Z = 2 };

template<int BNW, int EPI>
__global__ void __launch_bounds__(256, 2) gemm_k(
    const uint2* __restrict__ At, const uint2* __restrict__ Bt,
    const float* __restrict__ cb, int S, int Nout,
    float* __restrict__ Cout, int ldc,
    float* __restrict__ sptr, float* __restrict__ hfp,
    uint2* __restrict__ t1, int kwoff1, int S1,
    uint2* __restrict__ t2, int kwoff2, int S2,
    uint2* __restrict__ t3, int kwoff3, int S3,
    const float* __restrict__ epsp)
{
    constexpr int BSTR = (BNW == 128) ? 136 : 72;
    constexpr int BTWc = 16 * BSTR;
    constexpr int NI = BNW / 16;
    constexpr int STW = ATW + BTWc;
    extern __shared__ uint2 smp[];
    float* sbias = (float*)(smp + NSTG * STW);

    PDL_WAIT();

    const int tid = threadIdx.x, lane = tid & 31, w = tid >> 5;
    const int r = lane >> 2, j = lane & 3;
    const int wm = (w >> 1) * 32, wn = (w & 1) * (BNW / 2);
    const int m0 = blockIdx.y * 128, n0 = blockIdx.x * BNW;
    const uint2* Ag = At + (size_t)blockIdx.y * S * ATW;
    const uint2* Bg = Bt + (size_t)blockIdx.x * S * BTWc;
    if (tid < BNW) sbias[tid] = cb[n0 + tid];
    uint32_t smb = (uint32_t)__cvta_generic_to_shared(smp);

    const int aX = ((4 - j) & 3) << 2;
    const int pA0 = j * 1088 + ((wm + r) ^ aX) * 8;
    const int pA8 = j * 1088 + ((wm + r + 8) ^ aX) * 8;
    const int pB0 = j * (BSTR * 8) + ((wn + r) ^ aX) * 8;
    const int pB8 = j * (BSTR * 8) + ((wn + r + 8) ^ aX) * 8;

    float d[2][NI][4];
#pragma unroll
    for (int mi = 0; mi < 2; mi++)
#pragma unroll
        for (int ni = 0; ni < NI; ni++)
#pragma unroll
            for (int q = 0; q < 4; q++) d[mi][ni][q] = 0.f;

#define ISSUE(s, buf) {                                                    \
    const char* ga = (const char*)(Ag + (size_t)(s) * ATW);                \
    const char* gb = (const char*)(Bg + (size_t)(s) * BTWc);               \
    uint32_t da = smb + (buf) * (STW * 8);                                 \
    uint32_t db = da + ATW * 8;                                            \
    for (int i = tid; i < 1088; i += 256) CPA16(da + i * 16, ga + i * 16); \
    for (int i = tid; i < BTWc / 2; i += 256) CPA16(db + i * 16, gb + i * 16); \
    asm volatile("cp.async.commit_group;" ::: "memory"); }

#define COMPUTE(buf) {                                                     \
    const char* cbse = (const char*)smp + (size_t)(buf) * (STW * 8);       \
    const char* A0 = cbse + pA0;                                           \
    const char* A8 = cbse + pA8;                                           \
    const char* B0 = cbse + ATW * 8 + pB0;                                 \
    const char* B8 = cbse + ATW * 8 + pB8;                                 \
    _Pragma("unroll")                                                      \
    for (int kk = 0; kk < 2; kk++) {                                       \
        uint32_t ah[2][4], al[2][4];                                       \
        _Pragma("unroll")                                                  \
        for (int mi = 0; mi < 2; mi++) {                                   \
            int c1 = mi * 128 + kk * 8704;                                 \
            uint2 w0 = *(const uint2*)(A0 + c1);                           \
            uint2 w1 = *(const uint2*)(A8 + c1);                           \
            uint2 w2 = *(const uint2*)(A0 + c1 + 4352);                    \
            uint2 w3 = *(const uint2*)(A8 + c1 + 4352);                    \
            ah[mi][0] = w0.x; ah[mi][1] = w1.x; ah[mi][2] = w2.x; ah[mi][3] = w3.x; \
            al[mi][0] = w0.y; al[mi][1] = w1.y; al[mi][2] = w2.y; al[mi][3] = w3.y; \
        }                                                                  \
        _Pragma("unroll")                                                  \
        for (int ni = 0; ni < NI; ni++) {                                  \
            const char* Bb = (ni & 1) ? B8 : B0;                           \
            int c2 = (ni >> 1) * 128 + kk * 8 * (BSTR * 8);                \
            uint2 u0 = *(const uint2*)(Bb + c2);                           \
            uint2 u1 = *(const uint2*)(Bb + c2 + 4 * (BSTR * 8));          \
            uint32_t bh[2] = {u0.x, u1.x};                                 \
            uint32_t bl[2] = {u0.y, u1.y};                                 \
            _Pragma("unroll")                                              \
            for (int mi = 0; mi < 2; mi++) {                               \
                mma_bf16(d[mi][ni], ah[mi], bl);                           \
                mma_bf16(d[mi][ni], al[mi], bh);                           \
                mma_bf16(d[mi][ni], ah[mi], bh);                           \
            }                                                              \
        }                                                                  \
    } }

    ISSUE(0, 0);
    ISSUE(1, 1);
    for (int s = 0; s < S; s++) {
        if (s < S - 1) asm volatile("cp.async.wait_group 1;" ::: "memory");
        else           asm volatile("cp.async.wait_group 0;" ::: "memory");
        __syncthreads();
        if (s + 2 < S) ISSUE(s + 2, (s + 2) % 3);
        COMPUTE(s % 3);
    }

    if (EPI == EPI_NONE) {
#pragma unroll
        for (int mi = 0; mi < 2; mi++) {
            int row = m0 + wm + mi * 16 + r;
#pragma unroll
            for (int ni = 0; ni < NI; ni++) {
                int col = wn + ni * 8 + 2 * j;
                int gcol = n0 + col;
                if (gcol < Nout) {
                    float bx = sbias[col], by = sbias[col + 1];
                    *(float2*)(Cout + (size_t)row * ldc + gcol) =
                        make_float2(d[mi][ni][0] + bx, d[mi][ni][1] + by);
                    *(float2*)(Cout + (size_t)(row + 8) * ldc + gcol) =
                        make_float2(d[mi][ni][2] + bx, d[mi][ni][3] + by);
                }
            }
        }
    } else if (EPI == EPI_LSTM) {
        const int NU = Nout >> 2;
#pragma unroll
        for (int mi = 0; mi < 2; mi++) {
            int rowA = m0 + wm + mi * 16 + r;
            int rowB = rowA + 8;
#pragma unroll
            for (int ni = 0; ni < NI; ni++) {
                int colA = wn + ni * 8 + 2 * j;
                float v0 = d[mi][ni][0] + sbias[colA];
                float v1 = d[mi][ni][1] + sbias[colA + 1];
                float v2 = d[mi][ni][2] + sbias[colA];
                float v3 = d[mi][ni][3] + sbias[colA + 1];
                float x0 = __shfl_xor_sync(0xffffffffu, v0, 1);
                float x1 = __shfl_xor_sync(0xffffffffu, v1, 1);
                float x2 = __shfl_xor_sync(0xffffffffu, v2, 1);
                float x3 = __shfl_xor_sync(0xffffffffu, v3, 1);
                int u = (n0 + colA) >> 2;
                bool act = ((j & 1) == 0) && (u < NU);
                float sA = 0.f, sB = 0.f;
                if (act) {
                    sA = sptr[(size_t)rowA * 400 + u];
                    sB = sptr[(size_t)rowB * 400 + u];
                }
                float cA = fsigm(v1) * sA + fsigm(v0) * ftanh(x0);
                float cB = fsigm(v3) * sB + fsigm(v2) * ftanh(x2);
                float hA = fsigm(x1) * ftanh(cA);
                float hB = fsigm(x3) * ftanh(cB);
                float hA2 = __shfl_xor_sync(0xffffffffu, hA, 2);
                float hB2 = __shfl_xor_sync(0xffffffffu, hB, 2);
                if (act) {
                    sptr[(size_t)rowA * 400 + u] = cA;
                    sptr[(size_t)rowB * 400 + u] = cB;
                    if (hfp) {
                        hfp[(size_t)rowA * 400 + u] = hA;
                        hfp[(size_t)rowB * 400 + u] = hB;
                    }
                }
                if (j == 0 && u < NU) {
                    int kw = u >> 1;
                    uint32_t hw, lw;
                    split2(hA, hA2, hw, lw);
                    uint2 wA = make_uint2(hw, lw);
                    split2(hB, hB2, hw, lw);
                    uint2 wB = make_uint2(hw, lw);
                    t1[a_idx(S1, rowA, kwoff1 + kw)] = wA;
                    t1[a_idx(S1, rowB, kwoff1 + kw)] = wB;
                    if (t2) {
                        t2[a_idx(S2, rowA, kwoff2 + kw)] = wA;
                        t2[a_idx(S2, rowB, kwoff2 + kw)] = wB;
                    }
                    if (t3) {
                        t3[a_idx(S3, rowA, kwoff3 + kw)] = wA;
                        t3[a_idx(S3, rowB, kwoff3 + kw)] = wB;
                    }
                }
            }
        }
    } else {  // EPI_Z
        const int NU = Nout >> 1;
#pragma unroll
        for (int mi = 0; mi < 2; mi++) {
            int rowA = m0 + wm + mi * 16 + r;
            int rowB = rowA + 8;
#pragma unroll
            for (int ni = 0; ni < NI; ni++) {
                int colA = wn + ni * 8 + 2 * j;
                float v0 = d[mi][ni][0] + sbias[colA];
                float v1 = d[mi][ni][1] + sbias[colA + 1];
                float v2 = d[mi][ni][2] + sbias[colA];
                float v3 = d[mi][ni][3] + sbias[colA + 1];
                int u = (n0 + colA) >> 1;
                float eA = 0.f, eB = 0.f;
                if (u < NU) {
                    eA = epsp[(size_t)rowA * 100 + u];
                    eB = epsp[(size_t)rowB * 100 + u];
                }
                float zA = v0 + __expf(v1) * eA;
                float zB = v2 + __expf(v3) * eB;
                float zA2 = __shfl_xor_sync(0xffffffffu, zA, 1);
                float zB2 = __shfl_xor_sync(0xffffffffu, zB, 1);
                if (((j & 1) == 0) && (u < NU)) {
                    int kw = u >> 1;
                    uint32_t hw, lw;
                    split2(zA, zA2, hw, lw);
                    t1[a_idx(S1, rowA, kwoff1 + kw)] = make_uint2(hw, lw);
                    split2(zB, zB2, hw, lw);
                    t1[a_idx(S1, rowB, kwoff1 + kw)] = make_uint2(hw, lw);
                }
            }
        }
    }
#undef ISSUE
#undef COMPUTE
}

// ============ fused canvas-write(prev step) + attention + glimpse ============
#define FRW_SMEM 50300
__global__ __launch_bounds__(256) void fused_rw(
    const float* __restrict__ x, float* __restrict__ c,
    const float* __restrict__ hdec, const float* __restrict__ wrg,
    const float* __restrict__ w_attn, const float* __restrict__ b_attn,
    uint2* __restrict__ et, int do_write)
{
    extern __shared__ float sm[];
    float* xs   = sm;
    float* xh   = sm + 4096;
    float* sFyT = sm + 8192;     // [a*16+n]
    float* sFyW = sm + 9216;     // [n*64+a]
    float* sFx  = sm + 9984;     // [n*68+a]
    float* tmp0 = sm + 10800;
    float* tmp1 = sm + 11568;
    float* sw   = sm + 12336;
    float* red  = sm + 12480;
    float* pp   = sm + 12520;
    float* rsx  = sm + 12528;
    float* rsyg = sm + 12540;
    float* rsyw = sm + 12552;

    PDL_WAIT();

    int b = blockIdx.x, tid = threadIdx.x;
    int lane = tid & 31, wid = tid >> 5;
    const float* xb = x + (size_t)b * 4096;
    float* cbp = c + (size_t)b * 4096;
    const float* h = hdec + (size_t)b * 400;

    for (int i = tid; i < 1024; i += 256)
        *(float4*)&xs[i * 4] = *(const float4*)(xb + i * 4);
    if (tid < 144) sw[tid] = wrg[(size_t)b * 144 + tid];

    float acc[5] = {0.f, 0.f, 0.f, 0.f, 0.f};
    for (int k = tid; k < 400; k += 256) {
        float hv = h[k];
#pragma unroll
        for (int q = 0; q < 5; q++) acc[q] += hv * w_attn[q * 400 + k];
    }
#pragma unroll
    for (int q = 0; q < 5; q++)
#pragma unroll
        for (int off = 16; off > 0; off >>= 1)
            acc[q] += __shfl_xor_sync(0xffffffffu, acc[q], off);
    if (lane == 0)
#pragma unroll
        for (int q = 0; q < 5; q++) red[q * 8 + wid] = acc[q];
    __syncthreads();
    if (tid < 5) {
        float s = 0.f;
#pragma unroll
        for (int ww = 0; ww < 8; ww++) s += red[tid * 8 + ww];
        pp[tid] = s + b_attn[tid];
    }
    __syncthreads();

    float gx = 32.5f * (pp[0] + 1.0f);
    float gy = 32.5f * (pp[1] + 1.0f);
    float inv2s2 = __fdividef(1.0f, 2.0f * __expf(pp[2]));
    float delta = (63.0f / 11.0f) * __expf(pp[3]);
    float gamma = __expf(pp[4]);
    float invg = __expf(-pp[4]);

    for (int e = tid; e < 768; e += 256) {
        int n = e >> 6, a = e & 63;
        float fa = (float)a;
        float base = ((float)n - 6.5f) * delta;
        float ty = (fa - (base + gy)) * inv2s2;
        float fy = __expf(-ty * ty);
        sFyT[a * 16 + n] = fy;
        sFyW[n * 64 + a] = fy;
        float tx = (fa - (base + gx)) * inv2s2;
        sFx[n * 68 + a] = __expf(-tx * tx);
    }
    __syncthreads();
    if (tid < 12) {
        float s = 0.f;
        for (int a = 0; a < 64; a++) s += sFx[tid * 68 + a];
        rsx[tid] = __fdividef(1.0f, s + 1e-9f);
    } else if (tid >= 16 && tid < 28) {
        int n = tid - 16;
        float s = 0.f;
        for (int a = 0; a < 64; a++) s += sFyW[n * 64 + a];
        float inv = __fdividef(1.0f, s + 1e-9f);
        rsyg[n] = gamma * inv;
        rsyw[n] = invg * inv;
    }
    __syncthreads();
    for (int e = tid; e < 768; e += 256) {
        int n = e >> 6, a = e & 63;
        sFx[n * 68 + a] *= rsx[n];
        sFyT[a * 16 + n] *= rsyg[n];
        sFyW[n * 64 + a] *= rsyw[n];
    }
    __syncthreads();

    for (int e = tid; e < 768; e += 256) {
        int m = e >> 6, Bi = e & 63;
        float s = 0.f;
#pragma unroll
        for (int n = 0; n < NN; n++) s += sFyW[n * 64 + Bi] * sw[n * NN + m];
        tmp0[e] = s;
    }
    __syncthreads();

    for (int p = tid; p < 1024; p += 256) {
        int Bi = p >> 4, aq = p & 15;
        int idx = Bi * 64 + aq * 4;
        float4 cv;
        if (do_write) {
            float4 a4 = make_float4(0.f, 0.f, 0.f, 0.f);
#pragma unroll
            for (int m = 0; m < NN; m++) {
                float t = tmp0[m * 64 + Bi];
                float4 f4 = *(const float4*)&sFx[m * 68 + aq * 4];
                a4.x += t * f4.x; a4.y += t * f4.y;
                a4.z += t * f4.z; a4.w += t * f4.w;
            }
            cv = *(float4*)&cbp[idx];
            cv.x += a4.x; cv.y += a4.y; cv.z += a4.z; cv.w += a4.w;
        } else {
            cv = make_float4(0.f, 0.f, 0.f, 0.f);
        }
        *(float4*)&cbp[idx] = cv;
        float4 xv = *(const float4*)&xs[idx];
        float4 hv;
        hv.x = xv.x - fsigm(cv.x);
        hv.y = xv.y - fsigm(cv.y);
        hv.z = xv.z - fsigm(cv.z);
        hv.w = xv.w - fsigm(cv.w);
        *(float4*)&xh[idx] = hv;
    }
    __syncthreads();

    if (tid < 64) {
        int img = tid >> 5, half = (tid >> 4) & 1, aq = tid & 15;
        const float* src = img ? xh : xs;
        float* tdst = img ? tmp1 : tmp0;
        float a6[6][4];
#pragma unroll
        for (int nn = 0; nn < 6; nn++)
#pragma unroll
            for (int q = 0; q < 4; q++) a6[nn][q] = 0.f;
        for (int bi = 0; bi < 64; bi++) {
            float4 sv = *(const float4*)&src[bi * 64 + aq * 4];
            const float* fp = &sFyT[bi * 16 + half * 6];
#pragma unroll
            for (int nn = 0; nn < 6; nn++) {
                float f = fp[nn];
                a6[nn][0] += f * sv.x; a6[nn][1] += f * sv.y;
                a6[nn][2] += f * sv.z; a6[nn][3] += f * sv.w;
            }
        }
#pragma unroll
        for (int nn = 0; nn < 6; nn++)
            *(float4*)&tdst[(half * 6 + nn) * 64 + aq * 4] =
                make_float4(a6[nn][0], a6[nn][1], a6[nn][2], a6[nn][3]);
    }
    __syncthreads();

    for (int p = tid; p < 144; p += 256) {
        int img = p >= 72;
        int rem0 = 2 * p - img * 144;
        int n0q = rem0 / 12, m0q = rem0 - 12 * n0q;
        int n1q = n0q, m1q = m0q + 1;
        if (m1q == 12) { n1q++; m1q = 0; }
        const float* tsel = img ? tmp1 : tmp0;
        float s0 = 0.f, s1 = 0.f;
#pragma unroll
        for (int aq = 0; aq < 16; aq++) {
            float4 t0 = *(const float4*)&tsel[n0q * 64 + aq * 4];
            float4 f0 = *(const float4*)&sFx[m0q * 68 + aq * 4];
            s0 += t0.x * f0.x + t0.y * f0.y + t0.z * f0.z + t0.w * f0.w;
            float4 t1 = *(const float4*)&tsel[n1q * 64 + aq * 4];
            float4 f1 = *(const float4*)&sFx[m1q * 68 + aq * 4];
            s1 += t1.x * f1.x + t1.y * f1.y + t1.z * f1.z + t1.w * f1.w;
        }
        uint32_t hh, ll;
        split2(s0, s1, hh, ll);
        et[a_idx(S_ENC, b, p)] = make_uint2(hh, ll);
    }
}

// ============ final canvas write ============
__global__ __launch_bounds__(256) void write_final(
    const float* __restrict__ wrg, const float* __restrict__ hdec,
    const float* __restrict__ w_attn, const float* __restrict__ b_attn,
    float* __restrict__ c)
{
    __shared__ float sFy[NN * 64], sFx[NN * 64];
    __shared__ float sw[NN * NN];
    __shared__ float tmpv[NN * 64];
    __shared__ float red[5][8], pp[5], rsx[12], rsy[12];

    PDL_WAIT();

    int b = blockIdx.x;
    int tid = threadIdx.x;
    int lane = tid & 31, wid = tid >> 5;
    const float* h = hdec + (size_t)b * 400;

    float acc[5] = {0.f, 0.f, 0.f, 0.f, 0.f};
    for (int k = tid; k < 400; k += 256) {
        float hv = h[k];
#pragma unroll
        for (int q = 0; q < 5; q++) acc[q] += hv * w_attn[q * 400 + k];
    }
#pragma unroll
    for (int q = 0; q < 5; q++)
#pragma unroll
        for (int off = 16; off > 0; off >>= 1)
            acc[q] += __shfl_xor_sync(0xffffffffu, acc[q], off);
    if (lane == 0)
#pragma unroll
        for (int q = 0; q < 5; q++) red[q][wid] = acc[q];
    if (tid < NN * NN) sw[tid] = wrg[(size_t)b * (NN * NN) + tid];
    __syncthreads();
    if (tid < 5) {
        float s = 0.f;
#pragma unroll
        for (int ww = 0; ww < 8; ww++) s += red[tid][ww];
        pp[tid] = s + b_attn[tid];
    }
    __syncthreads();

    float gx = 32.5f * (pp[0] + 1.0f);
    float gy = 32.5f * (pp[1] + 1.0f);
    float inv2s2 = __fdividef(1.0f, 2.0f * __expf(pp[2]));
    float delta = (63.0f / 11.0f) * __expf(pp[3]);
    float invgamma = __expf(-pp[4]);

    for (int e = tid; e < 768; e += 256) {
        int n = e >> 6, a = e & 63;
        float fa = (float)a;
        float base = ((float)n - 6.5f) * delta;
        float ty = (fa - (base + gy)) * inv2s2;
        sFy[n * 64 + a] = __expf(-ty * ty);
        float tx = (fa - (base + gx)) * inv2s2;
        sFx[n * 64 + a] = __expf(-tx * tx);
    }
    __syncthreads();
    if (tid < 12) {
        float s = 0.f;
        for (int a = 0; a < 64; a++) s += sFx[tid * 64 + a];
        rsx[tid] = __fdividef(1.0f, s + 1e-9f);
    } else if (tid >= 16 && tid < 28) {
        int n = tid - 16;
        float s = 0.f;
        for (int a = 0; a < 64; a++) s += sFy[n * 64 + a];
        rsy[n] = invgamma * __fdividef(1.0f, s + 1e-9f);
    }
    __syncthreads();
    for (int e = tid; e < 768; e += 256) {
        int n = e >> 6, a = e & 63;
        sFx[n * 64 + a] *= rsx[n];
        sFy[n * 64 + a] *= rsy[n];
    }
    __syncthreads();

    for (int e = tid; e < NN * 64; e += 256) {
        int m = e >> 6, Bi = e & 63;
        float s = 0.f;
#pragma unroll
        for (int n = 0; n < NN; n++) s += sFy[n * 64 + Bi] * sw[n * NN + m];
        tmpv[e] = s;
    }
    __syncthreads();

    float* cbp = c + (size_t)b * 4096;
    for (int p = tid; p < 1024; p += 256) {
        int Bi = p >> 4, aq = p & 15;
        float4 a4 = make_float4(0.f, 0.f, 0.f, 0.f);
#pragma unroll
        for (int m = 0; m < NN; m++) {
            float t = tmpv[m * 64 + Bi];
            float4 f4 = *(const float4*)&sFx[m * 64 + aq * 4];
            a4.x += t * f4.x; a4.y += t * f4.y;
            a4.z += t * f4.z; a4.w += t * f4.w;
        }
        float4 cv = *(float4*)&cbp[Bi * 64 + aq * 4];
        cv.x += a4.x; cv.y += a4.y; cv.z += a4.z; cv.w += a4.w;
        *(float4*)&cbp[Bi * 64 + aq * 4] = cv;
    }
}

// ============ host ============
#define GS128 (NSTG * (ATW + 2176) * 8 + 1024)
#define GS64  (NSTG * (ATW + 1152) * 8 + 1024)

template<typename... Args>
static void pdl_launch(void (*kfn)(Args...), dim3 g, dim3 b, size_t smem,
                       Args... a)
{
    void* ptrs[] = { (void*)&a... };
    cudaLaunchConfig_t cfg;
    cfg.gridDim = g;
    cfg.blockDim = b;
    cfg.dynamicSmemBytes = smem;
    cfg.stream = 0;
    cudaLaunchAttribute at;
    at.id = cudaLaunchAttributeProgrammaticStreamSerialization;
    at.val.programmaticStreamSerializationAllowed = 1;
    cfg.attrs = &at;
    cfg.numAttrs = 1;
    cudaLaunchKernelExC(&cfg, (const void*)kfn, ptrs);
}

extern "C" void kernel_launch(void* const* d_in, const int* in_sizes, int n_in,
                              void* d_out, int out_size)
{
    const float* x        = (const float*)d_in[0];
    const float* eps      = (const float*)d_in[1];
    const float* w_enc_ih = (const float*)d_in[2];
    const float* w_enc_hh = (const float*)d_in[3];
    const float* b_enc_ih = (const float*)d_in[4];
    const float* b_enc_hh = (const float*)d_in[5];
    const float* w_dec_ih = (const float*)d_in[6];
    const float* w_dec_hh = (const float*)d_in[7];
    const float* b_dec_ih = (const float*)d_in[8];
    const float* b_dec_hh = (const float*)d_in[9];
    const float* w_mu     = (const float*)d_in[10];
    const float* b_mu     = (const float*)d_in[11];
    const float* w_sig    = (const float*)d_in[12];
    const float* b_sig    = (const float*)d_in[13];
    const float* w_attn   = (const float*)d_in[14];
    const float* b_attn   = (const float*)d_in[15];
    const float* w_write  = (const float*)d_in[16];
    const float* b_write  = (const float*)d_in[17];
    float* c = (float*)d_out;

    float *p_senc, *p_sdec, *p_hdec, *p_wrbuf;
    uint2 *p_enc0, *p_enc1, *p_dec0, *p_dec1, *p_henct, *p_hdect;
    uint2 *p_wenc, *p_wdec, *p_wms, *p_wwr;
    float *p_cbenc, *p_cbdec, *p_cbms, *p_cbwr;
    cudaGetSymbolAddress((void**)&p_senc,  g_senc);
    cudaGetSymbolAddress((void**)&p_sdec,  g_sdec);
    cudaGetSymbolAddress((void**)&p_hdec,  g_hdec);
    cudaGetSymbolAddress((void**)&p_wrbuf, g_wrbuf);
    cudaGetSymbolAddress((void**)&p_enc0,  g_encin0);
    cudaGetSymbolAddress((void**)&p_enc1,  g_encin1);
    cudaGetSymbolAddress((void**)&p_dec0,  g_decin0);
    cudaGetSymbolAddress((void**)&p_dec1,  g_decin1);
    cudaGetSymbolAddress((void**)&p_henct, g_henct);
    cudaGetSymbolAddress((void**)&p_hdect, g_hdect);
    cudaGetSymbolAddress((void**)&p_wenc,  g_wenc);
    cudaGetSymbolAddress((void**)&p_wdec,  g_wdec);
    cudaGetSymbolAddress((void**)&p_wms,   g_wms);
    cudaGetSymbolAddress((void**)&p_wwr,   g_wwr);
    cudaGetSymbolAddress((void**)&p_cbenc, g_cbenc);
    cudaGetSymbolAddress((void**)&p_cbdec, g_cbdec);
    cudaGetSymbolAddress((void**)&p_cbms,  g_cbms);
    cudaGetSymbolAddress((void**)&p_cbwr,  g_cbwr);

    cudaFuncSetAttribute(gemm_k<128, EPI_LSTM>,
                         cudaFuncAttributeMaxDynamicSharedMemorySize, GS128);
    cudaFuncSetAttribute(gemm_k<64, EPI_Z>,
                         cudaFuncAttributeMaxDynamicSharedMemorySize, GS64);
    cudaFuncSetAttribute(gemm_k<64, EPI_NONE>,
                         cudaFuncAttributeMaxDynamicSharedMemorySize, GS64);
    cudaFuncSetAttribute(fused_rw,
                         cudaFuncAttributeMaxDynamicSharedMemorySize, FRW_SMEM);

    zero_all<<<4096, 256>>>();
    prep_all<<<741, 256>>>(w_enc_ih, w_enc_hh, b_enc_ih, b_enc_hh,
                           w_dec_ih, w_dec_hh, b_dec_ih, b_dec_hh,
                           w_mu, b_mu, w_sig, b_sig, w_write, b_write,
                           p_wenc, p_cbenc, p_wdec, p_cbdec,
                           p_wms, p_cbms, p_wwr, p_cbwr);

    dim3 grid_gate(13, 32), grid_ms(4, 32), grid_wr(3, 32), blk(256);
    const uint2* nu2c = nullptr;
    uint2* nu2 = nullptr;
    float* nfl = nullptr;
    const float* nflc = nullptr;

    for (int t = 0; t < T_STEPS; t++) {
        uint2* enc_p = (t & 1) ? p_enc1 : p_enc0;
        uint2* enc_q = (t & 1) ? p_enc0 : p_enc1;
        uint2* dec_p = (t & 1) ? p_dec1 : p_dec0;
        uint2* dec_q = (t & 1) ? p_dec0 : p_dec1;

        pdl_launch(fused_rw, dim3(BATCH), blk, (size_t)FRW_SMEM,
                   x, c, (const float*)p_hdec, (const float*)p_wrbuf,
                   w_attn, b_attn, enc_p, (int)(t > 0));
        pdl_launch(gemm_k<128, EPI_LSTM>, grid_gate, blk, (size_t)GS128,
                   (const uint2*)enc_p, (const uint2*)p_wenc,
                   (const float*)p_cbenc, (int)S_ENC, 1600,
                   nfl, 0, p_senc, nfl,
                   p_henct, 0, (int)S_H, enc_q, 344, (int)S_ENC,
                   nu2, 0, 0, nflc);
        pdl_launch(gemm_k<64, EPI_Z>, grid_ms, blk, (size_t)GS64,
                   (const uint2*)p_henct, (const uint2*)p_wms,
                   (const float*)p_cbms, (int)S_H, 200,
                   nfl, 0, nfl, nfl,
                   dec_p, 0, (int)S_DEC, nu2, 0, 0, nu2, 0, 0,
                   (const float*)(eps + (size_t)t * BATCH * 100));
        pdl_launch(gemm_k<128, EPI_LSTM>, grid_gate, blk, (size_t)GS128,
                   (const uint2*)dec_p, (const uint2*)p_wdec,
                   (const float*)p_cbdec, (int)S_DEC, 1600,
                   nfl, 0, p_sdec, p_hdec,
                   dec_q, 50, (int)S_DEC, enc_q, 144, (int)S_ENC,
                   p_hdect, 0, (int)S_H, nflc);
        pdl_launch(gemm_k<64, EPI_NONE>, grid_wr, blk, (size_t)GS64,
                   (const uint2*)p_hdect, (const uint2*)p_wwr,
                   (const float*)p_cbwr, (int)S_H, 144,
                   p_wrbuf, 144, nfl, nfl,
                   nu2, 0, 0, nu2, 0, 0, nu2, 0, 0, nflc);
        (void)nu2c;
    }
    pdl_launch(write_final, dim3(BATCH), blk, (size_t)0,
               (const float*)p_wrbuf, (const float*)p_hdec,
               w_attn, b_attn, c);
}